// round 13
// baseline (speedup 1.0000x reference)
#include <cuda_runtime.h>
#include <cstdint>

#define DD 32          // embed dim
#define GI_W 96        // 3*DD gate width
#define NSYM 64        // distinct path symbol values

typedef uint32_t u32;

// ---------------------------------------------------------------------------
// Precomputed tables (device globals: no dynamic allocation allowed)
// ---------------------------------------------------------------------------
// Plain GIT (for k_h1): W_ih @ x + b_ih (+ b_hh for j<64)
__device__ float g_GIT[2][NSYM][GI_W];
// Slot-major GIT for MMA kernels: [tab][sym][slot][m], slot = 2c+pp
// (c: 0=r,1=z,2=n). float4 [slot][m] holds gate cols 32c+16pp+8ntl+2m+e at
// component 2*ntl+e. A quad (m=0..3) reads 64B contiguous.
__device__ float4 g_GIT3[2][NSYM][6][4];
__device__ float g_H1[NSYM * DD];          // GRU state after step 1 (key b0)
__device__ float g_H2[NSYM * NSYM * DD];   // GRU state after 2 steps, key (b0,b1)
// W_hh B fragments under the k-permutation pi(b, p) = 8b + 2p (p<4) /
// 8b + 2(p-4) + 1 (p>=4): A fragment of the next step == lane's own C frag.
// Layout [lane][2*nt+kp] so one lane's 24 frags are contiguous (LDG.128 x24).
__device__ float4 g_Bfrag[32][24];
__device__ float  g_bhn[DD];               // b_hh[64..95] (n-gate hidden bias)
__device__ float  g_wlr[DD];               // tf32-rounded w_lin

// ---------------------------------------------------------------------------
// TF32 emulation (reference matmuls are TF32 tensor-core GEMMs)
// ---------------------------------------------------------------------------
__device__ __forceinline__ float tf32r(float x) {
    float r;
    asm("cvt.rna.tf32.f32 %0, %1;" : "=f"(r) : "f"(x));
    return r;
}

// MUFU-native activations (abs err ~1e-5, proven negligible vs TF32 floor)
__device__ __forceinline__ float tanh_mufu(float x) {
    float r;
    asm("tanh.approx.f32 %0, %1;" : "=f"(r) : "f"(x));
    return r;
}
__device__ __forceinline__ float sig_mufu(float x) {
    return fmaf(0.5f, tanh_mufu(0.5f * x), 0.5f);
}

// tf32 MMA: D(16x8) += A(16x8) * B(8x8), fp32 accumulate
__device__ __forceinline__ void mma8(float c[4], const u32 a[4], u32 b0, u32 b1) {
    asm volatile(
        "mma.sync.aligned.m16n8k8.row.col.f32.tf32.tf32.f32 "
        "{%0,%1,%2,%3}, {%4,%5,%6,%7}, {%8,%9}, {%0,%1,%2,%3};"
        : "+f"(c[0]), "+f"(c[1]), "+f"(c[2]), "+f"(c[3])
        : "r"(a[0]), "r"(a[1]), "r"(a[2]), "r"(a[3]), "r"(b0), "r"(b1));
}

// ---------------------------------------------------------------------------
// One MMA GRU step, 16 paths/warp, shuffle-free, B entirely in registers
// (Bf[2*nt+kp], hoisted for the whole kernel). gp0/gp1 = GIT3 lane pointers.
// ---------------------------------------------------------------------------
__device__ __forceinline__ void gru_step_mma(
        float h_c[4][4], const float4* __restrict__ gp0,
        const float4* __restrict__ gp1, const float4 (&Bf)[24],
        const float* __restrict__ sBhn, int m) {
    // A fragments: a0=(grp,m)=h_c[b][0], a1=(grp+8,m)=h_c[b][2],
    //              a2=(grp,m+4)=h_c[b][1], a3=(grp+8,m+4)=h_c[b][3]
    u32 Ah[4][4];
    #pragma unroll
    for (int b = 0; b < 4; b++) {
        Ah[b][0] = __float_as_uint(tf32r(h_c[b][0]));
        Ah[b][1] = __float_as_uint(tf32r(h_c[b][2]));
        Ah[b][2] = __float_as_uint(tf32r(h_c[b][1]));
        Ah[b][3] = __float_as_uint(tf32r(h_c[b][3]));
    }

    float rn[4][4];   // r, then n in place

    // --- r gates (GIT3 slots 0..1, B frags 0..3): c init = gi_r+b_ih+b_hh ---
    #pragma unroll
    for (int pp = 0; pp < 2; pp++) {
        float4 ga = __ldg(gp0 + 4 * pp);
        float4 gb = __ldg(gp1 + 4 * pp);
        float ci[2][4] = {{ga.x, ga.y, gb.x, gb.y}, {ga.z, ga.w, gb.z, gb.w}};
        #pragma unroll
        for (int ntl = 0; ntl < 2; ntl++) {
            int nt = 2 * pp + ntl;
            float4 b0 = Bf[2 * nt + 0];
            float4 b1 = Bf[2 * nt + 1];
            mma8(ci[ntl], Ah[0], __float_as_uint(b0.x), __float_as_uint(b0.y));
            mma8(ci[ntl], Ah[1], __float_as_uint(b0.z), __float_as_uint(b0.w));
            mma8(ci[ntl], Ah[2], __float_as_uint(b1.x), __float_as_uint(b1.y));
            mma8(ci[ntl], Ah[3], __float_as_uint(b1.z), __float_as_uint(b1.w));
            rn[nt][0] = sig_mufu(ci[ntl][0]);
            rn[nt][1] = sig_mufu(ci[ntl][1]);
            rn[nt][2] = sig_mufu(ci[ntl][2]);
            rn[nt][3] = sig_mufu(ci[ntl][3]);
        }
    }

    // --- n gates (GIT3 slots 4..5, B frags 8..11): n = tanh(r*gh_n + gi_n) ---
    #pragma unroll
    for (int pp = 0; pp < 2; pp++) {
        float4 ga = __ldg(gp0 + 16 + 4 * pp);
        float4 gb = __ldg(gp1 + 16 + 4 * pp);
        float gi[2][4] = {{ga.x, ga.y, gb.x, gb.y}, {ga.z, ga.w, gb.z, gb.w}};
        #pragma unroll
        for (int ntl = 0; ntl < 2; ntl++) {
            int nt = 2 * pp + ntl;
            float2 bb = *(const float2*)&sBhn[8 * nt + 2 * m];
            float ch[4] = {bb.x, bb.y, bb.x, bb.y};
            float4 b0 = Bf[2 * (8 + nt) + 0];
            float4 b1 = Bf[2 * (8 + nt) + 1];
            mma8(ch, Ah[0], __float_as_uint(b0.x), __float_as_uint(b0.y));
            mma8(ch, Ah[1], __float_as_uint(b0.z), __float_as_uint(b0.w));
            mma8(ch, Ah[2], __float_as_uint(b1.x), __float_as_uint(b1.y));
            mma8(ch, Ah[3], __float_as_uint(b1.z), __float_as_uint(b1.w));
            rn[nt][0] = tanh_mufu(fmaf(rn[nt][0], ch[0], gi[ntl][0]));
            rn[nt][1] = tanh_mufu(fmaf(rn[nt][1], ch[1], gi[ntl][1]));
            rn[nt][2] = tanh_mufu(fmaf(rn[nt][2], ch[2], gi[ntl][2]));
            rn[nt][3] = tanh_mufu(fmaf(rn[nt][3], ch[3], gi[ntl][3]));
        }
    }

    // --- z gates (GIT3 slots 2..3, B frags 4..7) + update h = n + z*(h-n) ---
    #pragma unroll
    for (int pp = 0; pp < 2; pp++) {
        float4 ga = __ldg(gp0 + 8 + 4 * pp);
        float4 gb = __ldg(gp1 + 8 + 4 * pp);
        float ci[2][4] = {{ga.x, ga.y, gb.x, gb.y}, {ga.z, ga.w, gb.z, gb.w}};
        #pragma unroll
        for (int ntl = 0; ntl < 2; ntl++) {
            int nt = 2 * pp + ntl;
            float4 b0 = Bf[2 * (4 + nt) + 0];
            float4 b1 = Bf[2 * (4 + nt) + 1];
            mma8(ci[ntl], Ah[0], __float_as_uint(b0.x), __float_as_uint(b0.y));
            mma8(ci[ntl], Ah[1], __float_as_uint(b0.z), __float_as_uint(b0.w));
            mma8(ci[ntl], Ah[2], __float_as_uint(b1.x), __float_as_uint(b1.y));
            mma8(ci[ntl], Ah[3], __float_as_uint(b1.z), __float_as_uint(b1.w));
            #pragma unroll
            for (int e = 0; e < 4; e++) {
                float z = sig_mufu(ci[ntl][e]);
                float n = rn[nt][e];
                h_c[nt][e] = fmaf(z, h_c[nt][e] - n, n);
            }
        }
    }
}

// ---------------------------------------------------------------------------
// K_setup: fused zero + GIT/GIT3 + Bfrag(W_hh, permuted) + b_hh_n + w_lin.
// ---------------------------------------------------------------------------
__global__ void k_setup(float* out, int out_size,
                        const float* __restrict__ all_emb,
                        const float* __restrict__ edge_emb,
                        const float* __restrict__ w_ih,
                        const float* __restrict__ w_hh,
                        const float* __restrict__ b_ih,
                        const float* __restrict__ b_hh,
                        const float* __restrict__ w_lin) {
    int i = blockIdx.x * blockDim.x + threadIdx.x;
    if (i < 1024) {
        for (int k = i; k < out_size; k += 1024) out[k] = 0.0f;
        return;
    }
    int g = i - 1024;
    if (g < 12288) {               // GIT: TF32 products, fp64 sum, biases folded
        int tab = g / 6144, rem = g % 6144;
        int sym = rem / GI_W, j = rem % GI_W;
        const float* x = tab ? (edge_emb + sym * DD) : (all_emb + sym * DD);
        const float* w = w_ih + j * DD;
        double acc = 0.0;
        #pragma unroll
        for (int k = 0; k < DD; k++)
            acc += (double)tf32r(__ldg(w + k)) * (double)tf32r(__ldg(x + k));
        acc += (double)__ldg(b_ih + j);
        if (j < 64) acc += (double)__ldg(b_hh + j);   // fold b_hh for r/z gates
        float v = (float)acc;
        g_GIT[tab][sym][j] = v;
        // slot-major copy: col j = 32c + 16pp + 8ntl + 2m + e
        //   -> GIT3[tab][sym][2c+pp][m] component 2*ntl+e
        int c = j >> 5, r5 = j & 31;
        int pp = r5 >> 4, r4 = r5 & 15;
        int ntl = r4 >> 3, r3 = r4 & 7;
        int mm = r3 >> 1, e = r3 & 1;
        float* dst = (float*)&g_GIT3[tab][sym][0][0];
        dst[((2 * c + pp) * 4 + mm) * 4 + 2 * ntl + e] = v;
        return;
    }
    int j = i - 13312;
    if (j >= 0 && j < 768) {       // W_hh B fragments with pi permutation:
        int lane = j & 31;         //   block b, pos p<4 -> col 8b+2p; p>=4 -> 8b+2(p-4)+1
        int r1 = j >> 5;           // 0..23
        int kp = r1 & 1;
        int nt = r1 >> 1;          // 0..11
        int row = 8 * nt + (lane >> 2);
        int q = lane & 3;
        g_Bfrag[lane][2 * nt + kp] = make_float4(
            tf32r(w_hh[row * DD + 16 * kp + 2 * q]),
            tf32r(w_hh[row * DD + 16 * kp + 2 * q + 1]),
            tf32r(w_hh[row * DD + 16 * kp + 8 + 2 * q]),
            tf32r(w_hh[row * DD + 16 * kp + 8 + 2 * q + 1]));
        return;
    }
    int k = i - 14080;
    if (k >= 0 && k < DD) { g_bhn[k] = b_hh[64 + k]; return; }
    int w = i - 14112;
    if (w >= 0 && w < DD) g_wlr[w] = tf32r(w_lin[w]);
}

// ---------------------------------------------------------------------------
// K_h1: step 1 from h0=0 — depends only on b0 (elementwise; biases pre-folded)
// ---------------------------------------------------------------------------
__global__ void k_h1(int dummy) {
    int i = blockIdx.x * blockDim.x + threadIdx.x;
    if (i >= NSYM * DD) return;
    int e0 = i >> 5, j = i & 31;
    const float* git = &g_GIT[0][e0][0];
    float r = sig_mufu(git[j]);
    float z = sig_mufu(git[32 + j]);
    float n = tanh_mufu(fmaf(r, g_bhn[j], git[64 + j]));
    g_H1[e0 * DD + j] = (1.0f - z) * n;
}

// ---------------------------------------------------------------------------
// K_h2: H2 table via MMA. One warp = 16 consecutive keys.
// ---------------------------------------------------------------------------
__global__ void __launch_bounds__(128) k_h2(int dummy) {
    __shared__ float sBhn[DD];
    int tid = threadIdx.x;
    if (tid < DD) sBhn[tid] = g_bhn[tid];
    __syncthreads();

    int warp = tid >> 5, lane = tid & 31;
    int m = lane & 3, grp = lane >> 2;

    float4 Bf[24];
    #pragma unroll
    for (int q = 0; q < 24; q++) Bf[q] = __ldg(&g_Bfrag[lane][q]);

    int kbase = (blockIdx.x * 4 + warp) * 16;
    int key0 = kbase + grp;
    int key1 = key0 + 8;

    float h_c[4][4];
    const float* H0 = g_H1 + (key0 >> 6) * DD;
    const float* H1 = g_H1 + (key1 >> 6) * DD;
    #pragma unroll
    for (int nt = 0; nt < 4; nt++) {
        float2 v0 = *(const float2*)(H0 + 8 * nt + 2 * m);
        float2 v1 = *(const float2*)(H1 + 8 * nt + 2 * m);
        h_c[nt][0] = v0.x; h_c[nt][1] = v0.y;
        h_c[nt][2] = v1.x; h_c[nt][3] = v1.y;
    }

    gru_step_mma(h_c, &g_GIT3[1][key0 & 63][0][m],
                 &g_GIT3[1][key1 & 63][0][m], Bf, sBhn, m);

    float* D0 = g_H2 + key0 * DD;
    float* D1 = g_H2 + key1 * DD;
    #pragma unroll
    for (int nt = 0; nt < 4; nt++) {
        *(float2*)(D0 + 8 * nt + 2 * m) = make_float2(h_c[nt][0], h_c[nt][1]);
        *(float2*)(D1 + 8 * nt + 2 * m) = make_float2(h_c[nt][2], h_c[nt][3]);
    }
}

// ---------------------------------------------------------------------------
// K_main: one warp = 16 paths; W_hh B fragments live in registers for the
// whole kernel (zero in-loop LDS). 3 MMA GRU steps + head + atomic sum.
// ---------------------------------------------------------------------------
__global__ void __launch_bounds__(128, 3) k_main(
        const int* __restrict__ path, const int* __restrict__ path_idx,
        const float* __restrict__ b_lin, float* __restrict__ out, int n_paths) {
    __shared__ float sBhn[DD];
    __shared__ float sWl[DD];

    int tid = threadIdx.x;
    if (tid < DD) sBhn[tid] = g_bhn[tid];
    else if (tid >= 64 && tid < 64 + DD) sWl[tid - 64] = g_wlr[tid - 64];
    __syncthreads();

    int lane = tid & 31;
    int m = lane & 3, grp = lane >> 2;

    // Hoist B fragments into registers for the whole kernel
    float4 Bf[24];
    #pragma unroll
    for (int q = 0; q < 24; q++) Bf[q] = __ldg(&g_Bfrag[lane][q]);

    int pbase = (blockIdx.x * 4 + (tid >> 5)) * 16;
    int n1 = n_paths - 1;

    // Load per-path symbols (packed) and H2 state
    int spk[2];                    // [half]: b2 | b3<<8 | b4<<16
    float h_c[4][4];
    #pragma unroll
    for (int hf = 0; hf < 2; hf++) {
        int p = min(pbase + grp + 8 * hf, n1);
        const int* P = path + p * 5;
        int b0 = __ldg(P + 0), b1 = __ldg(P + 1);
        spk[hf] = __ldg(P + 2) | (__ldg(P + 3) << 8) | (__ldg(P + 4) << 16);
        const float* H = g_H2 + (b0 * NSYM + b1) * DD;
        #pragma unroll
        for (int nt = 0; nt < 4; nt++) {
            float2 v = *(const float2*)(H + 8 * nt + 2 * m);
            h_c[nt][2 * hf + 0] = v.x;
            h_c[nt][2 * hf + 1] = v.y;
        }
    }

    #pragma unroll 1
    for (int t = 0; t < 3; t++) {
        int tab = (t == 1) ? 1 : 0;
        int sh = 8 * t;
        gru_step_mma(h_c, &g_GIT3[tab][(spk[0] >> sh) & 63][0][m],
                     &g_GIT3[tab][(spk[1] >> sh) & 63][0][m], Bf, sBhn, m);
    }

    // Head: s = tf32(h) . tf32(w_lin) + b_lin, quad-reduced
    float sc0 = 0.0f, sc1 = 0.0f;
    #pragma unroll
    for (int nt = 0; nt < 4; nt++) {
        float2 wl = *(const float2*)&sWl[8 * nt + 2 * m];
        sc0 = fmaf(tf32r(h_c[nt][0]), wl.x, sc0);
        sc0 = fmaf(tf32r(h_c[nt][1]), wl.y, sc0);
        sc1 = fmaf(tf32r(h_c[nt][2]), wl.x, sc1);
        sc1 = fmaf(tf32r(h_c[nt][3]), wl.y, sc1);
    }
    sc0 += __shfl_xor_sync(0xffffffffu, sc0, 1);
    sc0 += __shfl_xor_sync(0xffffffffu, sc0, 2);
    sc1 += __shfl_xor_sync(0xffffffffu, sc1, 1);
    sc1 += __shfl_xor_sync(0xffffffffu, sc1, 2);

    float bl = __ldg(b_lin);
    if (m == 0) {
        int p0 = pbase + grp;
        int p1 = p0 + 8;
        if (p0 < n_paths) atomicAdd(out + __ldg(path_idx + p0), sc0 + bl);
        if (p1 < n_paths) atomicAdd(out + __ldg(path_idx + p1), sc1 + bl);
    }
}

// ---------------------------------------------------------------------------
extern "C" void kernel_launch(void* const* d_in, const int* in_sizes, int n_in,
                              void* d_out, int out_size) {
    // inputs: 0 users, 1 path, 2 path_idx, 3 all_emb, 4 edge_emb, 5 virtual_emb,
    //         6 w_ih, 7 w_hh, 8 b_ih, 9 b_hh, 10 w_lin, 11 b_lin
    const int*   path     = (const int*)d_in[1];
    const int*   path_idx = (const int*)d_in[2];
    const float* all_emb  = (const float*)d_in[3];
    const float* edge_emb = (const float*)d_in[4];
    const float* w_ih     = (const float*)d_in[6];
    const float* w_hh     = (const float*)d_in[7];
    const float* b_ih     = (const float*)d_in[8];
    const float* b_hh     = (const float*)d_in[9];
    const float* w_lin    = (const float*)d_in[10];
    const float* b_lin    = (const float*)d_in[11];
    float* out = (float*)d_out;
    int n_paths = in_sizes[2];

    k_setup<<<56, 256>>>(out, out_size, all_emb, edge_emb, w_ih, w_hh,
                         b_ih, b_hh, w_lin);
    k_h1<<<2, 1024>>>(0);
    k_h2<<<64, 128>>>(0);
    int nblocks = (n_paths + 63) / 64;   // 64 paths per block (4 warps x 16)
    k_main<<<nblocks, 128>>>(path, path_idx, b_lin, out, n_paths);
}

// round 14
// speedup vs baseline: 1.6001x; 1.6001x over previous
#include <cuda_runtime.h>
#include <cstdint>

#define DD 32          // embed dim
#define GI_W 96        // 3*DD gate width
#define NSYM 64        // distinct path symbol values

typedef uint32_t u32;

// ---------------------------------------------------------------------------
// Precomputed tables (device globals: no dynamic allocation allowed)
// ---------------------------------------------------------------------------
// Slot-major GIT: [tab][sym][slot][m], slot = 2c+pp (c: 0=r,1=z,2=n).
// float4 [slot][m] holds gate cols 32c+16pp+8ntl+2m+e at component 2*ntl+e.
// Biases folded: r/z have +b_ih+b_hh, n has +b_ih.
__device__ float4 g_GIT3[2][NSYM][6][4];
__device__ float g_H2[NSYM * NSYM * DD];   // tf32-rounded GRU state after 2 steps
// W_hh B fragments under k-permutation pi(b,p) = 8b+2p (p<4) / 8b+2(p-4)+1:
// the A fragment of the next step equals the lane's own C fragment.
__device__ float4 g_Bfrag[12][2][32];
__device__ float  g_bhn[DD];               // b_hh[64..95] (n-gate hidden bias)
__device__ float  g_wlr[DD];               // tf32-rounded w_lin

// ---------------------------------------------------------------------------
// TF32 emulation (reference matmuls are TF32 tensor-core GEMMs)
// ---------------------------------------------------------------------------
__device__ __forceinline__ float tf32r(float x) {
    float r;
    asm("cvt.rna.tf32.f32 %0, %1;" : "=f"(r) : "f"(x));
    return r;
}

// MUFU-native activations (abs err ~1e-5, proven negligible vs TF32 floor)
__device__ __forceinline__ float tanh_mufu(float x) {
    float r;
    asm("tanh.approx.f32 %0, %1;" : "=f"(r) : "f"(x));
    return r;
}
__device__ __forceinline__ float sig_mufu(float x) {
    return fmaf(0.5f, tanh_mufu(0.5f * x), 0.5f);
}

// f16x2 pack/unpack (explicit ordering: lo in low half)
__device__ __forceinline__ u32 packh2(float lo, float hi) {
    u32 d;
    asm("{.reg .f16 l,h; cvt.rn.f16.f32 l,%1; cvt.rn.f16.f32 h,%2; mov.b32 %0,{l,h};}"
        : "=r"(d) : "f"(lo), "f"(hi));
    return d;
}
__device__ __forceinline__ void unpackh2(u32 d, float& lo, float& hi) {
    asm("{.reg .f16 l,h; mov.b32 {l,h},%2; cvt.f32.f16 %0,l; cvt.f32.f16 %1,h;}"
        : "=f"(lo), "=f"(hi) : "r"(d));
}

// tf32 MMA: D(16x8) += A(16x8) * B(8x8), fp32 accumulate
__device__ __forceinline__ void mma8(float c[4], const u32 a[4], u32 b0, u32 b1) {
    asm volatile(
        "mma.sync.aligned.m16n8k8.row.col.f32.tf32.tf32.f32 "
        "{%0,%1,%2,%3}, {%4,%5,%6,%7}, {%8,%9}, {%0,%1,%2,%3};"
        : "+f"(c[0]), "+f"(c[1]), "+f"(c[2]), "+f"(c[3])
        : "r"(a[0]), "r"(a[1]), "r"(a[2]), "r"(a[3]), "r"(b0), "r"(b1));
}

// ---------------------------------------------------------------------------
// One MMA GRU step on 2 m16-tiles (32 paths/warp). State = Ah: tf32 bit
// patterns in A-fragment layout (slot 0=hf0e0, 1=hf1e0, 2=hf0e1, 3=hf1e1),
// used directly as MMA operands AND read back (as floats) at the update.
// z gates computed before n, stored as raw pre-activations packed f16x2.
// Order: r(MMA+sig) -> z(MMA, pack) -> n(MMA+tanh) -> update (sig z, blend,
// tf32-round back into Ah). All MMAs precede any Ah write.
// ---------------------------------------------------------------------------
__device__ __forceinline__ void gru_step(
        u32 (*Ah)[4][4],                      // [2][4][4]
        const float4* __restrict__ gt,        // &g_GIT3[tab][0][0][0]
        int i00, int i01, int i10, int i11,   // sym*24 + m per (tile, half)
        const float4 (*sB)[2][32],
        const float* __restrict__ sBhn,
        int lane, int m) {
    float rn[2][4][4];
    u32   zpk[2][4][2];

    // --- r gates (slots 0..1, B frags 0..3) ---
    #pragma unroll
    for (int pp = 0; pp < 2; pp++) {
        float4 g00 = __ldg(gt + i00 + 4 * pp);
        float4 g01 = __ldg(gt + i01 + 4 * pp);
        float4 g10 = __ldg(gt + i10 + 4 * pp);
        float4 g11 = __ldg(gt + i11 + 4 * pp);
        #pragma unroll
        for (int ntl = 0; ntl < 2; ntl++) {
            int nt = 2 * pp + ntl;
            float4 b0 = sB[nt][0][lane];
            float4 b1 = sB[nt][1][lane];
            #pragma unroll
            for (int tt = 0; tt < 2; tt++) {
                float4 ga = tt ? g10 : g00;
                float4 gb = tt ? g11 : g01;
                float c[4];
                c[0] = ntl ? ga.z : ga.x; c[1] = ntl ? ga.w : ga.y;
                c[2] = ntl ? gb.z : gb.x; c[3] = ntl ? gb.w : gb.y;
                mma8(c, Ah[tt][0], __float_as_uint(b0.x), __float_as_uint(b0.y));
                mma8(c, Ah[tt][1], __float_as_uint(b0.z), __float_as_uint(b0.w));
                mma8(c, Ah[tt][2], __float_as_uint(b1.x), __float_as_uint(b1.y));
                mma8(c, Ah[tt][3], __float_as_uint(b1.z), __float_as_uint(b1.w));
                rn[tt][nt][0] = sig_mufu(c[0]);
                rn[tt][nt][1] = sig_mufu(c[1]);
                rn[tt][nt][2] = sig_mufu(c[2]);
                rn[tt][nt][3] = sig_mufu(c[3]);
            }
        }
    }

    // --- z gates (slots 2..3, B frags 4..7): raw pre-act packed f16x2 ---
    #pragma unroll
    for (int pp = 0; pp < 2; pp++) {
        float4 g00 = __ldg(gt + i00 + 8 + 4 * pp);
        float4 g01 = __ldg(gt + i01 + 8 + 4 * pp);
        float4 g10 = __ldg(gt + i10 + 8 + 4 * pp);
        float4 g11 = __ldg(gt + i11 + 8 + 4 * pp);
        #pragma unroll
        for (int ntl = 0; ntl < 2; ntl++) {
            int nt = 2 * pp + ntl;
            float4 b0 = sB[4 + nt][0][lane];
            float4 b1 = sB[4 + nt][1][lane];
            #pragma unroll
            for (int tt = 0; tt < 2; tt++) {
                float4 ga = tt ? g10 : g00;
                float4 gb = tt ? g11 : g01;
                float c[4];
                c[0] = ntl ? ga.z : ga.x; c[1] = ntl ? ga.w : ga.y;
                c[2] = ntl ? gb.z : gb.x; c[3] = ntl ? gb.w : gb.y;
                mma8(c, Ah[tt][0], __float_as_uint(b0.x), __float_as_uint(b0.y));
                mma8(c, Ah[tt][1], __float_as_uint(b0.z), __float_as_uint(b0.w));
                mma8(c, Ah[tt][2], __float_as_uint(b1.x), __float_as_uint(b1.y));
                mma8(c, Ah[tt][3], __float_as_uint(b1.z), __float_as_uint(b1.w));
                zpk[tt][nt][0] = packh2(c[0], c[1]);
                zpk[tt][nt][1] = packh2(c[2], c[3]);
            }
        }
    }

    // --- n gates (slots 4..5, B frags 8..11): n = tanh(r*gh_n + gi_n) ---
    #pragma unroll
    for (int pp = 0; pp < 2; pp++) {
        float4 g00 = __ldg(gt + i00 + 16 + 4 * pp);
        float4 g01 = __ldg(gt + i01 + 16 + 4 * pp);
        float4 g10 = __ldg(gt + i10 + 16 + 4 * pp);
        float4 g11 = __ldg(gt + i11 + 16 + 4 * pp);
        #pragma unroll
        for (int ntl = 0; ntl < 2; ntl++) {
            int nt = 2 * pp + ntl;
            float2 bb = *(const float2*)&sBhn[8 * nt + 2 * m];
            float4 b0 = sB[8 + nt][0][lane];
            float4 b1 = sB[8 + nt][1][lane];
            #pragma unroll
            for (int tt = 0; tt < 2; tt++) {
                float4 ga = tt ? g10 : g00;
                float4 gb = tt ? g11 : g01;
                float gi[4];
                gi[0] = ntl ? ga.z : ga.x; gi[1] = ntl ? ga.w : ga.y;
                gi[2] = ntl ? gb.z : gb.x; gi[3] = ntl ? gb.w : gb.y;
                float ch[4] = {bb.x, bb.y, bb.x, bb.y};
                mma8(ch, Ah[tt][0], __float_as_uint(b0.x), __float_as_uint(b0.y));
                mma8(ch, Ah[tt][1], __float_as_uint(b0.z), __float_as_uint(b0.w));
                mma8(ch, Ah[tt][2], __float_as_uint(b1.x), __float_as_uint(b1.y));
                mma8(ch, Ah[tt][3], __float_as_uint(b1.z), __float_as_uint(b1.w));
                rn[tt][nt][0] = tanh_mufu(fmaf(rn[tt][nt][0], ch[0], gi[0]));
                rn[tt][nt][1] = tanh_mufu(fmaf(rn[tt][nt][1], ch[1], gi[1]));
                rn[tt][nt][2] = tanh_mufu(fmaf(rn[tt][nt][2], ch[2], gi[2]));
                rn[tt][nt][3] = tanh_mufu(fmaf(rn[tt][nt][3], ch[3], gi[3]));
            }
        }
    }

    // --- update: z = sig(unpack), h = n + z*(h-n), tf32-round into Ah ---
    // C index e -> Ah slot: {0->0, 1->2, 2->1, 3->3}
    #pragma unroll
    for (int tt = 0; tt < 2; tt++) {
        #pragma unroll
        for (int nt = 0; nt < 4; nt++) {
            float za, zb, zc, zd;
            unpackh2(zpk[tt][nt][0], za, zb);
            unpackh2(zpk[tt][nt][1], zc, zd);
            float z0 = sig_mufu(za), z1 = sig_mufu(zb);
            float z2 = sig_mufu(zc), z3 = sig_mufu(zd);
            float h0 = __uint_as_float(Ah[tt][nt][0]);
            float h1 = __uint_as_float(Ah[tt][nt][2]);
            float h2 = __uint_as_float(Ah[tt][nt][1]);
            float h3 = __uint_as_float(Ah[tt][nt][3]);
            float n0 = rn[tt][nt][0], n1 = rn[tt][nt][1];
            float n2 = rn[tt][nt][2], n3 = rn[tt][nt][3];
            Ah[tt][nt][0] = __float_as_uint(tf32r(fmaf(z0, h0 - n0, n0)));
            Ah[tt][nt][2] = __float_as_uint(tf32r(fmaf(z1, h1 - n1, n1)));
            Ah[tt][nt][1] = __float_as_uint(tf32r(fmaf(z2, h2 - n2, n2)));
            Ah[tt][nt][3] = __float_as_uint(tf32r(fmaf(z3, h3 - n3, n3)));
        }
    }
}

// ---------------------------------------------------------------------------
// K_setup: fused zero + GIT3 (fp32: tf32 products are exact) + Bfrag + bhn + wl
// ---------------------------------------------------------------------------
__global__ void k_setup(float* out, int out_size,
                        const float* __restrict__ all_emb,
                        const float* __restrict__ edge_emb,
                        const float* __restrict__ w_ih,
                        const float* __restrict__ w_hh,
                        const float* __restrict__ b_ih,
                        const float* __restrict__ b_hh,
                        const float* __restrict__ w_lin) {
    int i = blockIdx.x * blockDim.x + threadIdx.x;
    if (i < 1024) {
        for (int k = i; k < out_size; k += 1024) out[k] = 0.0f;
        return;
    }
    int g = i - 1024;
    if (g < 12288) {               // GIT3: TF32 products, fp32 dual-acc, biases folded
        int tab = g / 6144, rem = g % 6144;
        int sym = rem / GI_W, j = rem % GI_W;
        const float* x = tab ? (edge_emb + sym * DD) : (all_emb + sym * DD);
        const float* w = w_ih + j * DD;
        float a0 = 0.0f, a1 = 0.0f;
        #pragma unroll
        for (int k = 0; k < 16; k++) {
            a0 = fmaf(tf32r(__ldg(w + 2 * k)),     tf32r(__ldg(x + 2 * k)),     a0);
            a1 = fmaf(tf32r(__ldg(w + 2 * k + 1)), tf32r(__ldg(x + 2 * k + 1)), a1);
        }
        float v = (a0 + a1) + __ldg(b_ih + j);
        if (j < 64) v += __ldg(b_hh + j);   // fold b_hh for r/z gates
        // slot-major: col j = 32c + 16pp + 8ntl + 2m + e
        //   -> GIT3[tab][sym][2c+pp][m] component 2*ntl+e
        int c = j >> 5, r5 = j & 31;
        int pp = r5 >> 4, r4 = r5 & 15;
        int ntl = r4 >> 3, r3 = r4 & 7;
        int mm = r3 >> 1, e = r3 & 1;
        float* dst = (float*)&g_GIT3[tab][sym][0][0];
        dst[((2 * c + pp) * 4 + mm) * 4 + 2 * ntl + e] = v;
        return;
    }
    int j = i - 13312;
    if (j >= 0 && j < 768) {       // W_hh B fragments with pi permutation
        int lane = j & 31;
        int r1 = j >> 5;           // 0..23
        int kp = r1 & 1;
        int nt = r1 >> 1;          // 0..11
        int row = 8 * nt + (lane >> 2);
        int q = lane & 3;
        g_Bfrag[nt][kp][lane] = make_float4(
            tf32r(w_hh[row * DD + 16 * kp + 2 * q]),
            tf32r(w_hh[row * DD + 16 * kp + 2 * q + 1]),
            tf32r(w_hh[row * DD + 16 * kp + 8 + 2 * q]),
            tf32r(w_hh[row * DD + 16 * kp + 8 + 2 * q + 1]));
        return;
    }
    int k = i - 14080;
    if (k >= 0 && k < DD) { g_bhn[k] = b_hh[64 + k]; return; }
    int w = i - 14112;
    if (w >= 0 && w < DD) g_wlr[w] = tf32r(w_lin[w]);
}

// ---------------------------------------------------------------------------
// K_h2: H2 table. h1 computed inline from GIT3 (step 1 from h0=0 is
// elementwise), then one MMA GRU step. One warp = 32 keys (2 tiles).
// ---------------------------------------------------------------------------
__global__ void __launch_bounds__(128) k_h2(int dummy) {
    __shared__ float4 sB[12][2][32];
    __shared__ float sBhn[DD];
    int tid = threadIdx.x;
    {
        const float4* src = &g_Bfrag[0][0][0];
        float4* dst = &sB[0][0][0];
        for (int i = tid; i < 768; i += 128) dst[i] = src[i];
        if (tid < DD) sBhn[tid] = g_bhn[tid];
    }
    __syncthreads();

    int lane = tid & 31, m = lane & 3, grp = lane >> 2;
    int kbase = (blockIdx.x * 4 + (tid >> 5)) * 32;

    u32 Ah[2][4][4];
    int sym[2][2];
    #pragma unroll
    for (int tt = 0; tt < 2; tt++) {
        #pragma unroll
        for (int hf = 0; hf < 2; hf++) {
            int key = kbase + 16 * tt + grp + 8 * hf;
            int e0 = key >> 6;
            sym[tt][hf] = key & 63;
            const float4* G = &g_GIT3[0][e0][0][m];
            float4 R0 = __ldg(G + 0),  R1 = __ldg(G + 4);
            float4 Z0 = __ldg(G + 8),  Z1 = __ldg(G + 12);
            float4 N0 = __ldg(G + 16), N1 = __ldg(G + 20);
            #pragma unroll
            for (int nt = 0; nt < 4; nt++) {
                int pp = nt >> 1, ntl = nt & 1;
                float4 R = pp ? R1 : R0;
                float4 Z = pp ? Z1 : Z0;
                float4 N = pp ? N1 : N0;
                #pragma unroll
                for (int e = 0; e < 2; e++) {
                    float rv = ntl ? (e ? R.w : R.z) : (e ? R.y : R.x);
                    float zv = ntl ? (e ? Z.w : Z.z) : (e ? Z.y : Z.x);
                    float nv = ntl ? (e ? N.w : N.z) : (e ? N.y : N.x);
                    float r = sig_mufu(rv);
                    float z = sig_mufu(zv);
                    float n = tanh_mufu(fmaf(r, sBhn[8 * nt + 2 * m + e], nv));
                    float h1 = (1.0f - z) * n;
                    Ah[tt][nt][(e ? 2 : 0) + hf] = __float_as_uint(tf32r(h1));
                }
            }
        }
    }

    gru_step(Ah, &g_GIT3[1][0][0][0],
             sym[0][0] * 24 + m, sym[0][1] * 24 + m,
             sym[1][0] * 24 + m, sym[1][1] * 24 + m,
             sB, sBhn, lane, m);

    #pragma unroll
    for (int tt = 0; tt < 2; tt++) {
        int key0 = kbase + 16 * tt + grp;
        int key1 = key0 + 8;
        float* D0 = g_H2 + key0 * DD;
        float* D1 = g_H2 + key1 * DD;
        #pragma unroll
        for (int nt = 0; nt < 4; nt++) {
            *(float2*)(D0 + 8 * nt + 2 * m) = make_float2(
                __uint_as_float(Ah[tt][nt][0]), __uint_as_float(Ah[tt][nt][2]));
            *(float2*)(D1 + 8 * nt + 2 * m) = make_float2(
                __uint_as_float(Ah[tt][nt][1]), __uint_as_float(Ah[tt][nt][3]));
        }
    }
}

// ---------------------------------------------------------------------------
// K_main: one warp = 32 paths (2 m16 tiles). tf32-valued state in Ah only.
// ---------------------------------------------------------------------------
__global__ void __launch_bounds__(128, 4) k_main(
        const int* __restrict__ path, const int* __restrict__ path_idx,
        const float* __restrict__ b_lin, float* __restrict__ out, int n_paths) {
    __shared__ float4 sB[12][2][32];
    __shared__ float sBhn[DD];
    __shared__ float sWl[DD];

    int tid = threadIdx.x;
    {
        const float4* src = &g_Bfrag[0][0][0];
        float4* dst = &sB[0][0][0];
        for (int i = tid; i < 768; i += 128) dst[i] = src[i];
        if (tid < DD) sBhn[tid] = g_bhn[tid];
        if (tid >= 64 && tid < 64 + DD) sWl[tid - 64] = g_wlr[tid - 64];
    }
    __syncthreads();

    int lane = tid & 31, m = lane & 3, grp = lane >> 2;
    int pbase = (blockIdx.x * 4 + (tid >> 5)) * 32;
    int n1 = n_paths - 1;

    int spk[2][2];                 // [tile][half]: b2 | b3<<8 | b4<<16
    u32 Ah[2][4][4];
    #pragma unroll
    for (int tt = 0; tt < 2; tt++) {
        #pragma unroll
        for (int hf = 0; hf < 2; hf++) {
            int p = min(pbase + 16 * tt + grp + 8 * hf, n1);
            const int* P = path + p * 5;
            int b0 = __ldg(P + 0), b1 = __ldg(P + 1);
            spk[tt][hf] = __ldg(P + 2) | (__ldg(P + 3) << 8) | (__ldg(P + 4) << 16);
            const float* H = g_H2 + (b0 * NSYM + b1) * DD;
            #pragma unroll
            for (int nt = 0; nt < 4; nt++) {
                float2 v = *(const float2*)(H + 8 * nt + 2 * m);
                Ah[tt][nt][0 + hf] = __float_as_uint(v.x);   // e0
                Ah[tt][nt][2 + hf] = __float_as_uint(v.y);   // e1
            }
        }
    }

    #pragma unroll 1
    for (int t = 0; t < 3; t++) {
        int tab = (t == 1) ? 1 : 0;
        int sh = 8 * t;
        gru_step(Ah, &g_GIT3[tab][0][0][0],
                 ((spk[0][0] >> sh) & 63) * 24 + m,
                 ((spk[0][1] >> sh) & 63) * 24 + m,
                 ((spk[1][0] >> sh) & 63) * 24 + m,
                 ((spk[1][1] >> sh) & 63) * 24 + m,
                 sB, sBhn, lane, m);
    }

    // Head: s = tf32(h) . tf32(w_lin) + b_lin — Ah already holds tf32(h)
    float bl = __ldg(b_lin);
    #pragma unroll
    for (int tt = 0; tt < 2; tt++) {
        float sc0 = 0.0f, sc1 = 0.0f;
        #pragma unroll
        for (int nt = 0; nt < 4; nt++) {
            float2 wl = *(const float2*)&sWl[8 * nt + 2 * m];
            sc0 = fmaf(__uint_as_float(Ah[tt][nt][0]), wl.x, sc0);
            sc0 = fmaf(__uint_as_float(Ah[tt][nt][2]), wl.y, sc0);
            sc1 = fmaf(__uint_as_float(Ah[tt][nt][1]), wl.x, sc1);
            sc1 = fmaf(__uint_as_float(Ah[tt][nt][3]), wl.y, sc1);
        }
        sc0 += __shfl_xor_sync(0xffffffffu, sc0, 1);
        sc0 += __shfl_xor_sync(0xffffffffu, sc0, 2);
        sc1 += __shfl_xor_sync(0xffffffffu, sc1, 1);
        sc1 += __shfl_xor_sync(0xffffffffu, sc1, 2);
        if (m == 0) {
            int p0 = pbase + 16 * tt + grp;
            int p1 = p0 + 8;
            if (p0 < n_paths) atomicAdd(out + __ldg(path_idx + p0), sc0 + bl);
            if (p1 < n_paths) atomicAdd(out + __ldg(path_idx + p1), sc1 + bl);
        }
    }
}

// ---------------------------------------------------------------------------
extern "C" void kernel_launch(void* const* d_in, const int* in_sizes, int n_in,
                              void* d_out, int out_size) {
    // inputs: 0 users, 1 path, 2 path_idx, 3 all_emb, 4 edge_emb, 5 virtual_emb,
    //         6 w_ih, 7 w_hh, 8 b_ih, 9 b_hh, 10 w_lin, 11 b_lin
    const int*   path     = (const int*)d_in[1];
    const int*   path_idx = (const int*)d_in[2];
    const float* all_emb  = (const float*)d_in[3];
    const float* edge_emb = (const float*)d_in[4];
    const float* w_ih     = (const float*)d_in[6];
    const float* w_hh     = (const float*)d_in[7];
    const float* b_ih     = (const float*)d_in[8];
    const float* b_hh     = (const float*)d_in[9];
    const float* w_lin    = (const float*)d_in[10];
    const float* b_lin    = (const float*)d_in[11];
    float* out = (float*)d_out;
    int n_paths = in_sizes[2];

    k_setup<<<56, 256>>>(out, out_size, all_emb, edge_emb, w_ih, w_hh,
                         b_ih, b_hh, w_lin);
    k_h2<<<32, 128>>>(0);
    int nblocks = (n_paths + 127) / 128;   // 128 paths per block (4 warps x 32)
    k_main<<<nblocks, 128>>>(path, path_idx, b_lin, out, n_paths);
}

// round 15
// speedup vs baseline: 1.7395x; 1.0871x over previous
#include <cuda_runtime.h>
#include <cstdint>

#define DD 32          // embed dim
#define GI_W 96        // 3*DD gate width
#define NSYM 64        // distinct path symbol values

typedef uint32_t u32;

// ---------------------------------------------------------------------------
// Precomputed tables (device globals: no dynamic allocation allowed)
// ---------------------------------------------------------------------------
// Slot-major GIT: [tab][sym][slot][m], slot = 2c+pp (c: 0=r,1=z,2=n).
// float4 [slot][m] holds gate cols 32c+16pp+8ntl+2m+e at component 2*ntl+e.
// Biases folded: r/z have +b_ih+b_hh, n has +b_ih.
__device__ float4 g_GIT3[2][NSYM][6][4];
__device__ float g_H2[NSYM * NSYM * DD];   // tf32-rounded GRU state after 2 steps
// W_hh B fragments under k-permutation pi(b,p) = 8b+2p (p<4) / 8b+2(p-4)+1:
// the A fragment of the next step equals the lane's own C fragment.
__device__ float4 g_Bfrag[12][2][32];
__device__ float  g_bhn[DD];               // b_hh[64..95] (n-gate hidden bias)
__device__ float  g_wlr[DD];               // tf32-rounded w_lin

// ---------------------------------------------------------------------------
// TF32 emulation (reference matmuls are TF32 tensor-core GEMMs)
// ---------------------------------------------------------------------------
__device__ __forceinline__ float tf32r(float x) {
    float r;
    asm("cvt.rna.tf32.f32 %0, %1;" : "=f"(r) : "f"(x));
    return r;
}

// MUFU-native activations (abs err ~1e-5, proven negligible vs TF32 floor)
__device__ __forceinline__ float tanh_mufu(float x) {
    float r;
    asm("tanh.approx.f32 %0, %1;" : "=f"(r) : "f"(x));
    return r;
}
__device__ __forceinline__ float sig_mufu(float x) {
    return fmaf(0.5f, tanh_mufu(0.5f * x), 0.5f);
}

// f16x2 pack/unpack (explicit ordering: lo in low half)
__device__ __forceinline__ u32 packh2(float lo, float hi) {
    u32 d;
    asm("{.reg .f16 l,h; cvt.rn.f16.f32 l,%1; cvt.rn.f16.f32 h,%2; mov.b32 %0,{l,h};}"
        : "=r"(d) : "f"(lo), "f"(hi));
    return d;
}
__device__ __forceinline__ void unpackh2(u32 d, float& lo, float& hi) {
    asm("{.reg .f16 l,h; mov.b32 {l,h},%2; cvt.f32.f16 %0,l; cvt.f32.f16 %1,h;}"
        : "=f"(lo), "=f"(hi) : "r"(d));
}

// tf32 MMA: D(16x8) += A(16x8) * B(8x8), fp32 accumulate
__device__ __forceinline__ void mma8(float c[4], const u32 a[4], u32 b0, u32 b1) {
    asm volatile(
        "mma.sync.aligned.m16n8k8.row.col.f32.tf32.tf32.f32 "
        "{%0,%1,%2,%3}, {%4,%5,%6,%7}, {%8,%9}, {%0,%1,%2,%3};"
        : "+f"(c[0]), "+f"(c[1]), "+f"(c[2]), "+f"(c[3])
        : "r"(a[0]), "r"(a[1]), "r"(a[2]), "r"(a[3]), "r"(b0), "r"(b1));
}

// ---------------------------------------------------------------------------
// One MMA GRU step on NT m16-tiles (16*NT paths/warp). State = Ah: tf32 bit
// patterns in A-fragment layout (slot 0=hf0e0, 1=hf1e0, 2=hf0e1, 3=hf1e1).
// z gates computed before n, stored as raw pre-activations packed f16x2.
// ix[tt][hf] = sym*24 + m (GIT3 lane offsets).
// ---------------------------------------------------------------------------
template<int NT>
__device__ __forceinline__ void gru_step(
        u32 (*Ah)[4][4],
        const float4* __restrict__ gt,        // &g_GIT3[tab][0][0][0]
        const int (&ix)[NT][2],
        const float4 (*sB)[2][32],
        const float* __restrict__ sBhn,
        int lane, int m) {
    float rn[NT][4][4];
    u32   zpk[NT][4][2];

    // --- r gates (slots 0..1, B frags 0..3) ---
    #pragma unroll
    for (int pp = 0; pp < 2; pp++) {
        float4 g[NT][2];
        #pragma unroll
        for (int tt = 0; tt < NT; tt++) {
            g[tt][0] = __ldg(gt + ix[tt][0] + 4 * pp);
            g[tt][1] = __ldg(gt + ix[tt][1] + 4 * pp);
        }
        #pragma unroll
        for (int ntl = 0; ntl < 2; ntl++) {
            int nt = 2 * pp + ntl;
            float4 b0 = sB[nt][0][lane];
            float4 b1 = sB[nt][1][lane];
            #pragma unroll
            for (int tt = 0; tt < NT; tt++) {
                float4 ga = g[tt][0], gb = g[tt][1];
                float c[4];
                c[0] = ntl ? ga.z : ga.x; c[1] = ntl ? ga.w : ga.y;
                c[2] = ntl ? gb.z : gb.x; c[3] = ntl ? gb.w : gb.y;
                mma8(c, Ah[tt][0], __float_as_uint(b0.x), __float_as_uint(b0.y));
                mma8(c, Ah[tt][1], __float_as_uint(b0.z), __float_as_uint(b0.w));
                mma8(c, Ah[tt][2], __float_as_uint(b1.x), __float_as_uint(b1.y));
                mma8(c, Ah[tt][3], __float_as_uint(b1.z), __float_as_uint(b1.w));
                rn[tt][nt][0] = sig_mufu(c[0]);
                rn[tt][nt][1] = sig_mufu(c[1]);
                rn[tt][nt][2] = sig_mufu(c[2]);
                rn[tt][nt][3] = sig_mufu(c[3]);
            }
        }
    }

    // --- z gates (slots 2..3, B frags 4..7): raw pre-act packed f16x2 ---
    #pragma unroll
    for (int pp = 0; pp < 2; pp++) {
        float4 g[NT][2];
        #pragma unroll
        for (int tt = 0; tt < NT; tt++) {
            g[tt][0] = __ldg(gt + ix[tt][0] + 8 + 4 * pp);
            g[tt][1] = __ldg(gt + ix[tt][1] + 8 + 4 * pp);
        }
        #pragma unroll
        for (int ntl = 0; ntl < 2; ntl++) {
            int nt = 2 * pp + ntl;
            float4 b0 = sB[4 + nt][0][lane];
            float4 b1 = sB[4 + nt][1][lane];
            #pragma unroll
            for (int tt = 0; tt < NT; tt++) {
                float4 ga = g[tt][0], gb = g[tt][1];
                float c[4];
                c[0] = ntl ? ga.z : ga.x; c[1] = ntl ? ga.w : ga.y;
                c[2] = ntl ? gb.z : gb.x; c[3] = ntl ? gb.w : gb.y;
                mma8(c, Ah[tt][0], __float_as_uint(b0.x), __float_as_uint(b0.y));
                mma8(c, Ah[tt][1], __float_as_uint(b0.z), __float_as_uint(b0.w));
                mma8(c, Ah[tt][2], __float_as_uint(b1.x), __float_as_uint(b1.y));
                mma8(c, Ah[tt][3], __float_as_uint(b1.z), __float_as_uint(b1.w));
                zpk[tt][nt][0] = packh2(c[0], c[1]);
                zpk[tt][nt][1] = packh2(c[2], c[3]);
            }
        }
    }

    // --- n gates (slots 4..5, B frags 8..11): n = tanh(r*gh_n + gi_n) ---
    #pragma unroll
    for (int pp = 0; pp < 2; pp++) {
        float4 g[NT][2];
        #pragma unroll
        for (int tt = 0; tt < NT; tt++) {
            g[tt][0] = __ldg(gt + ix[tt][0] + 16 + 4 * pp);
            g[tt][1] = __ldg(gt + ix[tt][1] + 16 + 4 * pp);
        }
        #pragma unroll
        for (int ntl = 0; ntl < 2; ntl++) {
            int nt = 2 * pp + ntl;
            float2 bb = *(const float2*)&sBhn[8 * nt + 2 * m];
            float4 b0 = sB[8 + nt][0][lane];
            float4 b1 = sB[8 + nt][1][lane];
            #pragma unroll
            for (int tt = 0; tt < NT; tt++) {
                float4 ga = g[tt][0], gb = g[tt][1];
                float gi[4];
                gi[0] = ntl ? ga.z : ga.x; gi[1] = ntl ? ga.w : ga.y;
                gi[2] = ntl ? gb.z : gb.x; gi[3] = ntl ? gb.w : gb.y;
                float ch[4] = {bb.x, bb.y, bb.x, bb.y};
                mma8(ch, Ah[tt][0], __float_as_uint(b0.x), __float_as_uint(b0.y));
                mma8(ch, Ah[tt][1], __float_as_uint(b0.z), __float_as_uint(b0.w));
                mma8(ch, Ah[tt][2], __float_as_uint(b1.x), __float_as_uint(b1.y));
                mma8(ch, Ah[tt][3], __float_as_uint(b1.z), __float_as_uint(b1.w));
                rn[tt][nt][0] = tanh_mufu(fmaf(rn[tt][nt][0], ch[0], gi[0]));
                rn[tt][nt][1] = tanh_mufu(fmaf(rn[tt][nt][1], ch[1], gi[1]));
                rn[tt][nt][2] = tanh_mufu(fmaf(rn[tt][nt][2], ch[2], gi[2]));
                rn[tt][nt][3] = tanh_mufu(fmaf(rn[tt][nt][3], ch[3], gi[3]));
            }
        }
    }

    // --- update: z = sig(unpack), h = n + z*(h-n), tf32-round into Ah ---
    // C index e -> Ah slot: {0->0, 1->2, 2->1, 3->3}
    #pragma unroll
    for (int tt = 0; tt < NT; tt++) {
        #pragma unroll
        for (int nt = 0; nt < 4; nt++) {
            float za, zb, zc, zd;
            unpackh2(zpk[tt][nt][0], za, zb);
            unpackh2(zpk[tt][nt][1], zc, zd);
            float z0 = sig_mufu(za), z1 = sig_mufu(zb);
            float z2 = sig_mufu(zc), z3 = sig_mufu(zd);
            float h0 = __uint_as_float(Ah[tt][nt][0]);
            float h1 = __uint_as_float(Ah[tt][nt][2]);
            float h2 = __uint_as_float(Ah[tt][nt][1]);
            float h3 = __uint_as_float(Ah[tt][nt][3]);
            float n0 = rn[tt][nt][0], n1 = rn[tt][nt][1];
            float n2 = rn[tt][nt][2], n3 = rn[tt][nt][3];
            Ah[tt][nt][0] = __float_as_uint(tf32r(fmaf(z0, h0 - n0, n0)));
            Ah[tt][nt][2] = __float_as_uint(tf32r(fmaf(z1, h1 - n1, n1)));
            Ah[tt][nt][1] = __float_as_uint(tf32r(fmaf(z2, h2 - n2, n2)));
            Ah[tt][nt][3] = __float_as_uint(tf32r(fmaf(z3, h3 - n3, n3)));
        }
    }
}

// ---------------------------------------------------------------------------
// K_setup: fused zero + GIT3 + Bfrag + bhn + wl. GIT3 uses 4 threads per
// entry (8 MACs each + quad shfl-reduce) to quadruple latency hiding.
// segments: [0,49152) GIT3 | [49152,50176) zero | [50176,50944) Bfrag
//           [50944,50976) bhn | [50976,51008) wl
// ---------------------------------------------------------------------------
__global__ void k_setup(float* out, int out_size,
                        const float* __restrict__ all_emb,
                        const float* __restrict__ edge_emb,
                        const float* __restrict__ w_ih,
                        const float* __restrict__ w_hh,
                        const float* __restrict__ b_ih,
                        const float* __restrict__ b_hh,
                        const float* __restrict__ w_lin) {
    int i = blockIdx.x * blockDim.x + threadIdx.x;
    if (i < 49152) {               // GIT3: 4 threads per entry
        int entry = i >> 2, sub = i & 3;
        int tab = entry / 6144, rem = entry % 6144;
        int sym = rem / GI_W, j = rem % GI_W;
        const float* x = tab ? (edge_emb + sym * DD) : (all_emb + sym * DD);
        const float* w = w_ih + j * DD;
        float a = 0.0f;
        #pragma unroll
        for (int k = 0; k < 8; k++) {
            int kk = 8 * sub + k;
            a = fmaf(tf32r(__ldg(w + kk)), tf32r(__ldg(x + kk)), a);
        }
        a += __shfl_xor_sync(0xffffffffu, a, 1);
        a += __shfl_xor_sync(0xffffffffu, a, 2);
        if (sub == 0) {
            float v = a + __ldg(b_ih + j);
            if (j < 64) v += __ldg(b_hh + j);   // fold b_hh for r/z gates
            // slot-major: col j = 32c + 16pp + 8ntl + 2m + e
            //   -> GIT3[tab][sym][2c+pp][m] component 2*ntl+e
            int c = j >> 5, r5 = j & 31;
            int pp = r5 >> 4, r4 = r5 & 15;
            int ntl = r4 >> 3, r3 = r4 & 7;
            int mm = r3 >> 1, e = r3 & 1;
            float* dst = (float*)&g_GIT3[tab][sym][0][0];
            dst[((2 * c + pp) * 4 + mm) * 4 + 2 * ntl + e] = v;
        }
        return;
    }
    int z = i - 49152;
    if (z < 1024) {
        for (int k = z; k < out_size; k += 1024) out[k] = 0.0f;
        return;
    }
    int j = i - 50176;
    if (j >= 0 && j < 768) {       // W_hh B fragments with pi permutation
        int lane = j & 31;
        int r1 = j >> 5;           // 0..23
        int kp = r1 & 1;
        int nt = r1 >> 1;          // 0..11
        int row = 8 * nt + (lane >> 2);
        int q = lane & 3;
        g_Bfrag[nt][kp][lane] = make_float4(
            tf32r(w_hh[row * DD + 16 * kp + 2 * q]),
            tf32r(w_hh[row * DD + 16 * kp + 2 * q + 1]),
            tf32r(w_hh[row * DD + 16 * kp + 8 + 2 * q]),
            tf32r(w_hh[row * DD + 16 * kp + 8 + 2 * q + 1]));
        return;
    }
    int k = i - 50944;
    if (k >= 0 && k < DD) { g_bhn[k] = b_hh[64 + k]; return; }
    int w = i - 50976;
    if (w >= 0 && w < DD) g_wlr[w] = tf32r(w_lin[w]);
}

// ---------------------------------------------------------------------------
// K_h2: H2 table. h1 computed inline from GIT3 (step 1 from h0=0 is
// elementwise), then one MMA GRU step. NT=1: one warp = 16 keys (256 warps
// total -> 2x the parallelism of the NT=2 version; the kernel is latency-
// bound, not throughput-bound).
// ---------------------------------------------------------------------------
__global__ void __launch_bounds__(128) k_h2(int dummy) {
    __shared__ float4 sB[12][2][32];
    __shared__ float sBhn[DD];
    int tid = threadIdx.x;
    {
        const float4* src = &g_Bfrag[0][0][0];
        float4* dst = &sB[0][0][0];
        for (int i = tid; i < 768; i += 128) dst[i] = src[i];
        if (tid < DD) sBhn[tid] = g_bhn[tid];
    }
    __syncthreads();

    int lane = tid & 31, m = lane & 3, grp = lane >> 2;
    int kbase = (blockIdx.x * 4 + (tid >> 5)) * 16;

    u32 Ah[1][4][4];
    int ix[1][2];
    #pragma unroll
    for (int hf = 0; hf < 2; hf++) {
        int key = kbase + grp + 8 * hf;
        int e0 = key >> 6;
        ix[0][hf] = (key & 63) * 24 + m;
        const float4* G = &g_GIT3[0][e0][0][m];
        float4 R0 = __ldg(G + 0),  R1 = __ldg(G + 4);
        float4 Z0 = __ldg(G + 8),  Z1 = __ldg(G + 12);
        float4 N0 = __ldg(G + 16), N1 = __ldg(G + 20);
        #pragma unroll
        for (int nt = 0; nt < 4; nt++) {
            int pp = nt >> 1, ntl = nt & 1;
            float4 R = pp ? R1 : R0;
            float4 Z = pp ? Z1 : Z0;
            float4 N = pp ? N1 : N0;
            #pragma unroll
            for (int e = 0; e < 2; e++) {
                float rv = ntl ? (e ? R.w : R.z) : (e ? R.y : R.x);
                float zv = ntl ? (e ? Z.w : Z.z) : (e ? Z.y : Z.x);
                float nv = ntl ? (e ? N.w : N.z) : (e ? N.y : N.x);
                float r = sig_mufu(rv);
                float z = sig_mufu(zv);
                float n = tanh_mufu(fmaf(r, sBhn[8 * nt + 2 * m + e], nv));
                float h1 = (1.0f - z) * n;
                Ah[0][nt][(e ? 2 : 0) + hf] = __float_as_uint(tf32r(h1));
            }
        }
    }

    gru_step<1>(Ah, &g_GIT3[1][0][0][0], ix, sB, sBhn, lane, m);

    int key0 = kbase + grp;
    int key1 = key0 + 8;
    float* D0 = g_H2 + key0 * DD;
    float* D1 = g_H2 + key1 * DD;
    #pragma unroll
    for (int nt = 0; nt < 4; nt++) {
        *(float2*)(D0 + 8 * nt + 2 * m) = make_float2(
            __uint_as_float(Ah[0][nt][0]), __uint_as_float(Ah[0][nt][2]));
        *(float2*)(D1 + 8 * nt + 2 * m) = make_float2(
            __uint_as_float(Ah[0][nt][1]), __uint_as_float(Ah[0][nt][3]));
    }
}

// ---------------------------------------------------------------------------
// K_main: one warp = 32 paths (2 m16 tiles). tf32-valued state in Ah only.
// ---------------------------------------------------------------------------
__global__ void __launch_bounds__(128, 4) k_main(
        const int* __restrict__ path, const int* __restrict__ path_idx,
        const float* __restrict__ b_lin, float* __restrict__ out, int n_paths) {
    __shared__ float4 sB[12][2][32];
    __shared__ float sBhn[DD];
    __shared__ float sWl[DD];

    int tid = threadIdx.x;
    {
        const float4* src = &g_Bfrag[0][0][0];
        float4* dst = &sB[0][0][0];
        for (int i = tid; i < 768; i += 128) dst[i] = src[i];
        if (tid < DD) sBhn[tid] = g_bhn[tid];
        if (tid >= 64 && tid < 64 + DD) sWl[tid - 64] = g_wlr[tid - 64];
    }
    __syncthreads();

    int lane = tid & 31, m = lane & 3, grp = lane >> 2;
    int pbase = (blockIdx.x * 4 + (tid >> 5)) * 32;
    int n1 = n_paths - 1;

    int spk[2][2];                 // [tile][half]: b2 | b3<<8 | b4<<16
    u32 Ah[2][4][4];
    #pragma unroll
    for (int tt = 0; tt < 2; tt++) {
        #pragma unroll
        for (int hf = 0; hf < 2; hf++) {
            int p = min(pbase + 16 * tt + grp + 8 * hf, n1);
            const int* P = path + p * 5;
            int b0 = __ldg(P + 0), b1 = __ldg(P + 1);
            spk[tt][hf] = __ldg(P + 2) | (__ldg(P + 3) << 8) | (__ldg(P + 4) << 16);
            const float* H = g_H2 + (b0 * NSYM + b1) * DD;
            #pragma unroll
            for (int nt = 0; nt < 4; nt++) {
                float2 v = *(const float2*)(H + 8 * nt + 2 * m);
                Ah[tt][nt][0 + hf] = __float_as_uint(v.x);   // e0
                Ah[tt][nt][2 + hf] = __float_as_uint(v.y);   // e1
            }
        }
    }

    #pragma unroll 1
    for (int t = 0; t < 3; t++) {
        int tab = (t == 1) ? 1 : 0;
        int sh = 8 * t;
        int ix[2][2] = {
            {((spk[0][0] >> sh) & 63) * 24 + m, ((spk[0][1] >> sh) & 63) * 24 + m},
            {((spk[1][0] >> sh) & 63) * 24 + m, ((spk[1][1] >> sh) & 63) * 24 + m}};
        gru_step<2>(Ah, &g_GIT3[tab][0][0][0], ix, sB, sBhn, lane, m);
    }

    // Head: s = tf32(h) . tf32(w_lin) + b_lin — Ah already holds tf32(h)
    float bl = __ldg(b_lin);
    #pragma unroll
    for (int tt = 0; tt < 2; tt++) {
        float sc0 = 0.0f, sc1 = 0.0f;
        #pragma unroll
        for (int nt = 0; nt < 4; nt++) {
            float2 wl = *(const float2*)&sWl[8 * nt + 2 * m];
            sc0 = fmaf(__uint_as_float(Ah[tt][nt][0]), wl.x, sc0);
            sc0 = fmaf(__uint_as_float(Ah[tt][nt][2]), wl.y, sc0);
            sc1 = fmaf(__uint_as_float(Ah[tt][nt][1]), wl.x, sc1);
            sc1 = fmaf(__uint_as_float(Ah[tt][nt][3]), wl.y, sc1);
        }
        sc0 += __shfl_xor_sync(0xffffffffu, sc0, 1);
        sc0 += __shfl_xor_sync(0xffffffffu, sc0, 2);
        sc1 += __shfl_xor_sync(0xffffffffu, sc1, 1);
        sc1 += __shfl_xor_sync(0xffffffffu, sc1, 2);
        if (m == 0) {
            int p0 = pbase + 16 * tt + grp;
            int p1 = p0 + 8;
            if (p0 < n_paths) atomicAdd(out + __ldg(path_idx + p0), sc0 + bl);
            if (p1 < n_paths) atomicAdd(out + __ldg(path_idx + p1), sc1 + bl);
        }
    }
}

// ---------------------------------------------------------------------------
extern "C" void kernel_launch(void* const* d_in, const int* in_sizes, int n_in,
                              void* d_out, int out_size) {
    // inputs: 0 users, 1 path, 2 path_idx, 3 all_emb, 4 edge_emb, 5 virtual_emb,
    //         6 w_ih, 7 w_hh, 8 b_ih, 9 b_hh, 10 w_lin, 11 b_lin
    const int*   path     = (const int*)d_in[1];
    const int*   path_idx = (const int*)d_in[2];
    const float* all_emb  = (const float*)d_in[3];
    const float* edge_emb = (const float*)d_in[4];
    const float* w_ih     = (const float*)d_in[6];
    const float* w_hh     = (const float*)d_in[7];
    const float* b_ih     = (const float*)d_in[8];
    const float* b_hh     = (const float*)d_in[9];
    const float* w_lin    = (const float*)d_in[10];
    const float* b_lin    = (const float*)d_in[11];
    float* out = (float*)d_out;
    int n_paths = in_sizes[2];

    k_setup<<<200, 256>>>(out, out_size, all_emb, edge_emb, w_ih, w_hh,
                          b_ih, b_hh, w_lin);
    k_h2<<<64, 128>>>(0);
    int nblocks = (n_paths + 127) / 128;   // 128 paths per block (4 warps x 32)
    k_main<<<nblocks, 128>>>(path, path_idx, b_lin, out, n_paths);
}